// round 1
// baseline (speedup 1.0000x reference)
#include <cuda_runtime.h>
#include <math.h>
#include <stdint.h>

#define BN    4
#define TN    4096
#define EN    1024
#define DFFN  4096
#define NSTEP 128
#define KB    16

// ---------------- scratch (no allocations allowed) ----------------
__device__ float g_M[64 * 64];              // w_fft2 @ w_fft1
__device__ float g_cn[BN * 64 * EN];        // LN1 output
__device__ float g_cn2[BN * 64 * EN];       // LN2 output
__device__ float g_res2[BN * 64 * EN];      // fft + residual
__device__ float g_f[BN * 64 * DFFN];       // sin(gate)*val
__device__ float g_part[2 * BN * 64 * EN];  // split-K partials of GEMM2
__device__ float g_carry[BN * 32 * EN];     // proc[:,32:64] carried to next step

// ---------------- helpers ----------------
__device__ __forceinline__ float warp_red(float v) {
#pragma unroll
    for (int o = 16; o; o >>= 1) v += __shfl_xor_sync(0xffffffffu, v, o);
    return v;
}

// ---------------- M = w_fft2 (64x48) @ w_fft1 (48x64) ----------------
__global__ void k_precompute_M(const float* __restrict__ w1, const float* __restrict__ w2) {
    int idx = blockIdx.x * 256 + threadIdx.x;   // 0..4095
    int t = idx >> 6, tp = idx & 63;
    float acc = 0.f;
#pragma unroll
    for (int u = 0; u < 48; u++) acc += w2[t * 48 + u] * w1[u * 64 + tp];
    g_M[idx] = acc;
}

// ---------------- LN1 over mixed rows ----------------
// grid 256 blocks = b*64+t, 256 threads, 4 floats each
__global__ void k_ln1(const float* __restrict__ x, const float* __restrict__ w,
                      const float* __restrict__ bb, int step) {
    int b = blockIdx.x >> 6, t = blockIdx.x & 63;
    int e = threadIdx.x * 4;
    float4 v;
    if (t < 32) {
        const float* src = (step == 0) ? (x + ((size_t)b * TN + t) * EN)
                                       : (g_carry + ((size_t)b * 32 + t) * EN);
        v = *(const float4*)(src + e);
    } else {
        int r = step * 32 + t;
        if (r < TN) v = *(const float4*)(x + ((size_t)b * TN + r) * EN + e);
        else        v = make_float4(0.f, 0.f, 0.f, 0.f);
    }
    float s  = v.x + v.y + v.z + v.w;
    float ss = v.x * v.x + v.y * v.y + v.z * v.z + v.w * v.w;
    __shared__ float sb[8], sb2[8];
    float rs = warp_red(s), rss = warp_red(ss);
    int lane = threadIdx.x & 31, wid = threadIdx.x >> 5;
    if (lane == 0) { sb[wid] = rs; sb2[wid] = rss; }
    __syncthreads();
    float tot = 0.f, tot2 = 0.f;
#pragma unroll
    for (int i = 0; i < 8; i++) { tot += sb[i]; tot2 += sb2[i]; }
    float mu = tot * (1.f / EN);
    float rstd = rsqrtf(tot2 * (1.f / EN) - mu * mu + 1e-5f);
    float4 wv = *(const float4*)(w + e);
    float4 bv = *(const float4*)(bb + e);
    float4 o;
    o.x = (v.x - mu) * rstd * wv.x + bv.x;
    o.y = (v.y - mu) * rstd * wv.y + bv.y;
    o.z = (v.z - mu) * rstd * wv.z + bv.z;
    o.w = (v.w - mu) * rstd * wv.w + bv.w;
    *(float4*)(g_cn + (size_t)blockIdx.x * EN + e) = o;
}

// ---------------- fft = M @ cn ; res2 = fft + chunk ; LN2 ----------------
__global__ void k_fftln2(const float* __restrict__ x, const float* __restrict__ w,
                         const float* __restrict__ bb, int step) {
    int b = blockIdx.x >> 6, t = blockIdx.x & 63;
    int e = threadIdx.x * 4;
    __shared__ float sM[64];
    __shared__ float sb[8], sb2[8];
    if (threadIdx.x < 64) sM[threadIdx.x] = g_M[t * 64 + threadIdx.x];
    __syncthreads();
    float4 acc = make_float4(0.f, 0.f, 0.f, 0.f);
    const float* base = g_cn + (size_t)b * 64 * EN + e;
    for (int tp = 0; tp <= t; tp++) {   // M is lower-triangular
        float m = sM[tp];
        float4 c = *(const float4*)(base + (size_t)tp * EN);
        acc.x += m * c.x; acc.y += m * c.y; acc.z += m * c.z; acc.w += m * c.w;
    }
    int r = step * 32 + t;
    float4 xv = (r < TN) ? *(const float4*)(x + ((size_t)b * TN + r) * EN + e)
                         : make_float4(0.f, 0.f, 0.f, 0.f);
    float4 res;
    res.x = acc.x + xv.x; res.y = acc.y + xv.y; res.z = acc.z + xv.z; res.w = acc.w + xv.w;

    float s  = res.x + res.y + res.z + res.w;
    float ss = res.x * res.x + res.y * res.y + res.z * res.z + res.w * res.w;
    float rs = warp_red(s), rss = warp_red(ss);
    int lane = threadIdx.x & 31, wid = threadIdx.x >> 5;
    if (lane == 0) { sb[wid] = rs; sb2[wid] = rss; }
    __syncthreads();
    float tot = 0.f, tot2 = 0.f;
#pragma unroll
    for (int i = 0; i < 8; i++) { tot += sb[i]; tot2 += sb2[i]; }
    float mu = tot * (1.f / EN);
    float rstd = rsqrtf(tot2 * (1.f / EN) - mu * mu + 1e-5f);
    float4 wv = *(const float4*)(w + e);
    float4 bv = *(const float4*)(bb + e);
    float4 o;
    o.x = (res.x - mu) * rstd * wv.x + bv.x;
    o.y = (res.y - mu) * rstd * wv.y + bv.y;
    o.z = (res.z - mu) * rstd * wv.z + bv.z;
    o.w = (res.w - mu) * rstd * wv.w + bv.w;
    size_t row = (size_t)blockIdx.x * EN + e;
    *(float4*)(g_res2 + row) = res;
    *(float4*)(g_cn2 + row)  = o;
}

// ---------------- GEMM1: gv = cn2 @ w_up^T (+b_up), f = sin(gate)*val ----------------
// grid (DFFN/64, 256/64) = (64, 4), 256 threads, tile 64x64 (gate+val), micro 4x4
__global__ void __launch_bounds__(256) k_gemm1(const float* __restrict__ w_up,
                                               const float* __restrict__ b_up) {
    __shared__ float As[KB * 68], Gs[KB * 68], Vs[KB * 68];
    int n0 = blockIdx.x * 64;
    int m0 = blockIdx.y * 64;
    int tid = threadIdx.x;
    int lrow = tid >> 2, kq = tid & 3;
    int tx = tid & 15, ty = tid >> 4;

    const float* pa = g_cn2 + (size_t)(m0 + lrow) * EN + kq * 4;
    const float* pg = w_up + (size_t)(n0 + lrow) * EN + kq * 4;
    const float* pv = w_up + (size_t)(DFFN + n0 + lrow) * EN + kq * 4;

    float4 ra = *(const float4*)pa;
    float4 rg = *(const float4*)pg;
    float4 rv = *(const float4*)pv;

    float accg[4][4] = {}, accv[4][4] = {};

    for (int k0 = 0; k0 < EN; k0 += KB) {
        int kb = kq * 4;
        As[(kb + 0) * 68 + lrow] = ra.x; As[(kb + 1) * 68 + lrow] = ra.y;
        As[(kb + 2) * 68 + lrow] = ra.z; As[(kb + 3) * 68 + lrow] = ra.w;
        Gs[(kb + 0) * 68 + lrow] = rg.x; Gs[(kb + 1) * 68 + lrow] = rg.y;
        Gs[(kb + 2) * 68 + lrow] = rg.z; Gs[(kb + 3) * 68 + lrow] = rg.w;
        Vs[(kb + 0) * 68 + lrow] = rv.x; Vs[(kb + 1) * 68 + lrow] = rv.y;
        Vs[(kb + 2) * 68 + lrow] = rv.z; Vs[(kb + 3) * 68 + lrow] = rv.w;
        __syncthreads();
        if (k0 + KB < EN) {
            ra = *(const float4*)(pa + k0 + KB);
            rg = *(const float4*)(pg + k0 + KB);
            rv = *(const float4*)(pv + k0 + KB);
        }
#pragma unroll
        for (int kk = 0; kk < KB; kk++) {
            float4 a4 = *(const float4*)&As[kk * 68 + ty * 4];
            float4 g4 = *(const float4*)&Gs[kk * 68 + tx * 4];
            float4 v4 = *(const float4*)&Vs[kk * 68 + tx * 4];
            float av[4] = {a4.x, a4.y, a4.z, a4.w};
            float gg[4] = {g4.x, g4.y, g4.z, g4.w};
            float vv[4] = {v4.x, v4.y, v4.z, v4.w};
#pragma unroll
            for (int i = 0; i < 4; i++)
#pragma unroll
                for (int j = 0; j < 4; j++) {
                    accg[i][j] += av[i] * gg[j];
                    accv[i][j] += av[i] * vv[j];
                }
        }
        __syncthreads();
    }

    int n = n0 + tx * 4;
    float4 bug = *(const float4*)(b_up + n);
    float4 buv = *(const float4*)(b_up + DFFN + n);
#pragma unroll
    for (int i = 0; i < 4; i++) {
        int r = m0 + ty * 4 + i;
        float4 o;
        o.x = sinf(accg[i][0] + bug.x) * (accv[i][0] + buv.x);
        o.y = sinf(accg[i][1] + bug.y) * (accv[i][1] + buv.y);
        o.z = sinf(accg[i][2] + bug.z) * (accv[i][2] + buv.z);
        o.w = sinf(accg[i][3] + bug.w) * (accv[i][3] + buv.w);
        *(float4*)(g_f + (size_t)r * DFFN + n) = o;
    }
}

// ---------------- GEMM2: partial[z] = f @ w_down^T (split-K 2) ----------------
// grid (EN/64, 256/64, 2) = (16, 4, 2), 256 threads, tile 64x64, micro 4x4
__global__ void __launch_bounds__(256) k_gemm2(const float* __restrict__ w_down) {
    __shared__ float As[KB * 68], Ws[KB * 68];
    int n0 = blockIdx.x * 64;
    int m0 = blockIdx.y * 64;
    int z  = blockIdx.z;
    int tid = threadIdx.x;
    int lrow = tid >> 2, kq = tid & 3;
    int tx = tid & 15, ty = tid >> 4;

    const float* pa = g_f + (size_t)(m0 + lrow) * DFFN + z * 2048 + kq * 4;
    const float* pw = w_down + (size_t)(n0 + lrow) * DFFN + z * 2048 + kq * 4;

    float4 ra = *(const float4*)pa;
    float4 rw = *(const float4*)pw;
    float acc[4][4] = {};

    for (int k0 = 0; k0 < 2048; k0 += KB) {
        int kb = kq * 4;
        As[(kb + 0) * 68 + lrow] = ra.x; As[(kb + 1) * 68 + lrow] = ra.y;
        As[(kb + 2) * 68 + lrow] = ra.z; As[(kb + 3) * 68 + lrow] = ra.w;
        Ws[(kb + 0) * 68 + lrow] = rw.x; Ws[(kb + 1) * 68 + lrow] = rw.y;
        Ws[(kb + 2) * 68 + lrow] = rw.z; Ws[(kb + 3) * 68 + lrow] = rw.w;
        __syncthreads();
        if (k0 + KB < 2048) {
            ra = *(const float4*)(pa + k0 + KB);
            rw = *(const float4*)(pw + k0 + KB);
        }
#pragma unroll
        for (int kk = 0; kk < KB; kk++) {
            float4 a4 = *(const float4*)&As[kk * 68 + ty * 4];
            float4 w4 = *(const float4*)&Ws[kk * 68 + tx * 4];
            float av[4] = {a4.x, a4.y, a4.z, a4.w};
            float wv[4] = {w4.x, w4.y, w4.z, w4.w};
#pragma unroll
            for (int i = 0; i < 4; i++)
#pragma unroll
                for (int j = 0; j < 4; j++) acc[i][j] += av[i] * wv[j];
        }
        __syncthreads();
    }
#pragma unroll
    for (int i = 0; i < 4; i++) {
        int r = m0 + ty * 4 + i;
        float4 o = make_float4(acc[i][0], acc[i][1], acc[i][2], acc[i][3]);
        *(float4*)(g_part + ((size_t)z * BN * 64 + r) * EN + n0 + tx * 4) = o;
    }
}

// ---------------- epilogue: proc = p0+p1+b_down+res2 ; route out/carry ----------------
__global__ void k_epi(const float* __restrict__ b_down, float* __restrict__ out, int step) {
    int row = blockIdx.x;           // 0..255
    int b = row >> 6, t = row & 63;
    int e = threadIdx.x * 4;
    float4 p0 = *(const float4*)(g_part + (size_t)row * EN + e);
    float4 p1 = *(const float4*)(g_part + (size_t)(BN * 64 + row) * EN + e);
    float4 r2 = *(const float4*)(g_res2 + (size_t)row * EN + e);
    float4 bd = *(const float4*)(b_down + e);
    float4 o;
    o.x = p0.x + p1.x + bd.x + r2.x;
    o.y = p0.y + p1.y + bd.y + r2.y;
    o.z = p0.z + p1.z + bd.z + r2.z;
    o.w = p0.w + p1.w + bd.w + r2.w;
    if (t < 32)
        *(float4*)(out + ((size_t)b * TN + step * 32 + t) * EN + e) = o;
    else
        *(float4*)(g_carry + ((size_t)b * 32 + (t - 32)) * EN + e) = o;
}

// ---------------- launch ----------------
extern "C" void kernel_launch(void* const* d_in, const int* in_sizes, int n_in,
                              void* d_out, int out_size) {
    const float* x      = (const float*)d_in[0];
    const float* ln1_w  = (const float*)d_in[1];
    const float* ln1_b  = (const float*)d_in[2];
    const float* w_fft1 = (const float*)d_in[3];
    const float* w_fft2 = (const float*)d_in[4];
    const float* ln2_w  = (const float*)d_in[5];
    const float* ln2_b  = (const float*)d_in[6];
    const float* w_up   = (const float*)d_in[7];
    const float* b_up   = (const float*)d_in[8];
    const float* w_down = (const float*)d_in[9];
    const float* b_down = (const float*)d_in[10];
    float* out = (float*)d_out;

    k_precompute_M<<<16, 256>>>(w_fft1, w_fft2);
    for (int s = 0; s < NSTEP; s++) {
        k_ln1<<<256, 256>>>(x, ln1_w, ln1_b, s);
        k_fftln2<<<256, 256>>>(x, ln2_w, ln2_b, s);
        k_gemm1<<<dim3(64, 4), 256>>>(w_up, b_up);
        k_gemm2<<<dim3(16, 4, 2), 256>>>(w_down);
        k_epi<<<256, 256>>>(b_down, out, s);
    }
}

// round 3
// speedup vs baseline: 2.6436x; 2.6436x over previous
#include <cuda_runtime.h>
#include <cuda_bf16.h>
#include <math.h>
#include <stdint.h>

#define BN    4
#define TN    4096
#define EN    1024
#define DFFN  4096
#define NSTEP 128
#define SK    72          // smem tile stride in bf16 elems (144B, conflict-free)

// ---------------- scratch (no allocations allowed) ----------------
__device__ __align__(16) float g_M[64 * 64];
__device__ __align__(16) float g_cn[BN * 64 * EN];
__device__ __align__(16) float g_res2[BN * 64 * EN];
__device__ __align__(16) unsigned int g_cn2p[BN * 64 * EN];      // packed bf16 hi|lo
__device__ __align__(16) unsigned int g_fp[BN * 64 * DFFN];      // packed bf16 hi|lo
__device__ __align__(16) float g_part[8 * BN * 64 * EN];         // split-K partials
__device__ __align__(16) float g_carry[BN * 32 * EN];
__device__ __align__(16) __nv_bfloat16 g_wup_hi[2 * DFFN * EN];
__device__ __align__(16) __nv_bfloat16 g_wup_lo[2 * DFFN * EN];
__device__ __align__(16) __nv_bfloat16 g_wdn_hi[EN * DFFN];
__device__ __align__(16) __nv_bfloat16 g_wdn_lo[EN * DFFN];

// ---------------- helpers ----------------
__device__ __forceinline__ uint32_t smem_u32(const void* p) {
    uint32_t a;
    asm("{ .reg .u64 t; cvta.to.shared.u64 t, %1; cvt.u32.u64 %0, t; }" : "=r"(a) : "l"(p));
    return a;
}
__device__ __forceinline__ unsigned int pack_bf16split(float f) {
    __nv_bfloat16 h = __float2bfloat16(f);
    float fl = f - __bfloat162float(h);
    __nv_bfloat16 l = __float2bfloat16(fl);
    return (unsigned int)__bfloat16_as_ushort(h) | ((unsigned int)__bfloat16_as_ushort(l) << 16);
}
__device__ __forceinline__ float warp_red(float v) {
#pragma unroll
    for (int o = 16; o; o >>= 1) v += __shfl_xor_sync(0xffffffffu, v, o);
    return v;
}

#define CP_ASYNC(dst, src) \
    asm volatile("cp.async.cg.shared.global [%0], [%1], 16;" :: "r"(dst), "l"(src))
#define CP_COMMIT() asm volatile("cp.async.commit_group;" ::: "memory")
#define CP_WAIT0()  asm volatile("cp.async.wait_group 0;" ::: "memory")
#define CP_WAIT1()  asm volatile("cp.async.wait_group 1;" ::: "memory")

__device__ __forceinline__ void ldm_x4(uint32_t addr, uint32_t* r) {
    asm volatile("ldmatrix.sync.aligned.m8n8.x4.shared.b16 {%0,%1,%2,%3}, [%4];"
                 : "=r"(r[0]), "=r"(r[1]), "=r"(r[2]), "=r"(r[3]) : "r"(addr));
}
__device__ __forceinline__ void mma_bf16(float* c, const uint32_t* a, uint32_t b0, uint32_t b1) {
    asm volatile("mma.sync.aligned.m16n8k16.row.col.f32.bf16.bf16.f32 "
                 "{%0,%1,%2,%3}, {%4,%5,%6,%7}, {%8,%9}, {%0,%1,%2,%3};"
                 : "+f"(c[0]), "+f"(c[1]), "+f"(c[2]), "+f"(c[3])
                 : "r"(a[0]), "r"(a[1]), "r"(a[2]), "r"(a[3]), "r"(b0), "r"(b1));
}

// smem layout (dynamic): Ahi[128*SK], Alo[128*SK], then 2 stages of {Bhi, Blo}
#define PLANE_B   (128 * SK * 2)                 // 18432 bytes
#define SM_AHI    0
#define SM_ALO    PLANE_B
#define SM_B(s)   (2 * PLANE_B + (s) * 2 * PLANE_B)
#define SMEM_BYTES (6 * PLANE_B)                 // 110592

// ---------------- weight split ----------------
__global__ void k_convert_w(const float* __restrict__ wu, const float* __restrict__ wd) {
    size_t i4 = ((size_t)blockIdx.x * 256 + threadIdx.x) * 4;
    const size_t N1 = (size_t)2 * DFFN * EN;
    float4 v;
    __nv_bfloat16 *ph, *pl;
    if (i4 < N1) { v = *(const float4*)(wu + i4); ph = g_wup_hi + i4; pl = g_wup_lo + i4; }
    else { size_t j = i4 - N1; v = *(const float4*)(wd + j); ph = g_wdn_hi + j; pl = g_wdn_lo + j; }
    unsigned int p0 = pack_bf16split(v.x), p1 = pack_bf16split(v.y);
    unsigned int p2 = pack_bf16split(v.z), p3 = pack_bf16split(v.w);
    uint2 hi = make_uint2((p0 & 0xFFFFu) | (p1 << 16), (p2 & 0xFFFFu) | (p3 << 16));
    uint2 lo = make_uint2((p0 >> 16) | (p1 & 0xFFFF0000u), (p2 >> 16) | (p3 & 0xFFFF0000u));
    *(uint2*)ph = hi;
    *(uint2*)pl = lo;
}

// ---------------- M = w_fft2 @ w_fft1 ----------------
__global__ void k_precompute_M(const float* __restrict__ w1, const float* __restrict__ w2) {
    int idx = blockIdx.x * 256 + threadIdx.x;
    int t = idx >> 6, tp = idx & 63;
    float acc = 0.f;
#pragma unroll
    for (int u = 0; u < 48; u++) acc += w2[t * 48 + u] * w1[u * 64 + tp];
    g_M[idx] = acc;
}

// ---------------- LN1 ----------------
__global__ void k_ln1(const float* __restrict__ x, const float* __restrict__ w,
                      const float* __restrict__ bb, int step) {
    int b = blockIdx.x >> 6, t = blockIdx.x & 63;
    int e = threadIdx.x * 4;
    float4 v;
    if (t < 32) {
        const float* src = (step == 0) ? (x + ((size_t)b * TN + t) * EN)
                                       : (g_carry + ((size_t)b * 32 + t) * EN);
        v = *(const float4*)(src + e);
    } else {
        int r = step * 32 + t;
        if (r < TN) v = *(const float4*)(x + ((size_t)b * TN + r) * EN + e);
        else        v = make_float4(0.f, 0.f, 0.f, 0.f);
    }
    float s = v.x + v.y + v.z + v.w;
    float ss = v.x * v.x + v.y * v.y + v.z * v.z + v.w * v.w;
    __shared__ float sb[8], sb2[8];
    float rs = warp_red(s), rss = warp_red(ss);
    int lane = threadIdx.x & 31, wid = threadIdx.x >> 5;
    if (lane == 0) { sb[wid] = rs; sb2[wid] = rss; }
    __syncthreads();
    float tot = 0.f, tot2 = 0.f;
#pragma unroll
    for (int i = 0; i < 8; i++) { tot += sb[i]; tot2 += sb2[i]; }
    float mu = tot * (1.f / EN);
    float rstd = rsqrtf(tot2 * (1.f / EN) - mu * mu + 1e-5f);
    float4 wv = *(const float4*)(w + e);
    float4 bv = *(const float4*)(bb + e);
    float4 o;
    o.x = (v.x - mu) * rstd * wv.x + bv.x;
    o.y = (v.y - mu) * rstd * wv.y + bv.y;
    o.z = (v.z - mu) * rstd * wv.z + bv.z;
    o.w = (v.w - mu) * rstd * wv.w + bv.w;
    *(float4*)(g_cn + (size_t)blockIdx.x * EN + e) = o;
}

// ---------------- fft + res2 + LN2 -> packed bf16 split ----------------
__global__ void k_fftln2(const float* __restrict__ x, const float* __restrict__ w,
                         const float* __restrict__ bb, int step) {
    int b = blockIdx.x >> 6, t = blockIdx.x & 63;
    int e = threadIdx.x * 4;
    __shared__ float sM[64];
    __shared__ float sb[8], sb2[8];
    if (threadIdx.x < 64) sM[threadIdx.x] = g_M[t * 64 + threadIdx.x];
    __syncthreads();
    float4 acc = make_float4(0.f, 0.f, 0.f, 0.f);
    const float* base = g_cn + (size_t)b * 64 * EN + e;
    for (int tp = 0; tp <= t; tp++) {
        float m = sM[tp];
        float4 c = *(const float4*)(base + (size_t)tp * EN);
        acc.x += m * c.x; acc.y += m * c.y; acc.z += m * c.z; acc.w += m * c.w;
    }
    int r = step * 32 + t;
    float4 xv = (r < TN) ? *(const float4*)(x + ((size_t)b * TN + r) * EN + e)
                         : make_float4(0.f, 0.f, 0.f, 0.f);
    float4 res;
    res.x = acc.x + xv.x; res.y = acc.y + xv.y; res.z = acc.z + xv.z; res.w = acc.w + xv.w;
    float s = res.x + res.y + res.z + res.w;
    float ss = res.x * res.x + res.y * res.y + res.z * res.z + res.w * res.w;
    float rs = warp_red(s), rss = warp_red(ss);
    int lane = threadIdx.x & 31, wid = threadIdx.x >> 5;
    if (lane == 0) { sb[wid] = rs; sb2[wid] = rss; }
    __syncthreads();
    float tot = 0.f, tot2 = 0.f;
#pragma unroll
    for (int i = 0; i < 8; i++) { tot += sb[i]; tot2 += sb2[i]; }
    float mu = tot * (1.f / EN);
    float rstd = rsqrtf(tot2 * (1.f / EN) - mu * mu + 1e-5f);
    float4 wv = *(const float4*)(w + e);
    float4 bv = *(const float4*)(bb + e);
    size_t row = (size_t)blockIdx.x * EN + e;
    *(float4*)(g_res2 + row) = res;
    uint4 pk;
    pk.x = pack_bf16split((res.x - mu) * rstd * wv.x + bv.x);
    pk.y = pack_bf16split((res.y - mu) * rstd * wv.y + bv.y);
    pk.z = pack_bf16split((res.z - mu) * rstd * wv.z + bv.z);
    pk.w = pack_bf16split((res.w - mu) * rstd * wv.w + bv.w);
    *(uint4*)(g_cn2p + row) = pk;
}

// ---------------- GEMM building blocks ----------------
// prefetch packed-A tile (128 x 64 uint32) into regs
__device__ __forceinline__ void ldA_regs(const unsigned int* __restrict__ src, int strideA,
                                         int m0, int k0, int tid, uint4* r) {
#pragma unroll
    for (int it = 0; it < 8; it++) {
        int c = it * 256 + tid;
        int row = c >> 4, koff = (c & 15) * 4;
        r[it] = *(const uint4*)(src + (size_t)(m0 + row) * strideA + k0 + koff);
    }
}
// unpack regs -> Ahi/Alo smem planes
__device__ __forceinline__ void stA_unpack(uint32_t smAhi, uint32_t smAlo, int tid, const uint4* r) {
#pragma unroll
    for (int it = 0; it < 8; it++) {
        int c = it * 256 + tid;
        int row = c >> 4, koff = (c & 15) * 4;
        uint4 v = r[it];
        uint32_t h01 = (v.x & 0xFFFFu) | (v.y << 16);
        uint32_t h23 = (v.z & 0xFFFFu) | (v.w << 16);
        uint32_t l01 = (v.x >> 16) | (v.y & 0xFFFF0000u);
        uint32_t l23 = (v.z >> 16) | (v.w & 0xFFFF0000u);
        uint32_t off = (uint32_t)(row * SK + koff) * 2;
        asm volatile("st.shared.v2.u32 [%0], {%1,%2};" :: "r"(smAhi + off), "r"(h01), "r"(h23));
        asm volatile("st.shared.v2.u32 [%0], {%1,%2};" :: "r"(smAlo + off), "r"(l01), "r"(l23));
    }
}
// cp.async B tile (hi+lo planes, 128 rows x 64 k each)
template <int INTERLEAVE>
__device__ __forceinline__ void cpB(uint32_t smB, const __nv_bfloat16* __restrict__ hi,
                                    const __nv_bfloat16* __restrict__ lo,
                                    int strideB, int k0, int tid, int nbase) {
#pragma unroll
    for (int it = 0; it < 4; it++) {
        int c = it * 256 + tid;
        int row = c >> 3, koff = (c & 7) * 8;
        int grow;
        if (INTERLEAVE) grow = (row & 1) ? (DFFN + nbase + (row >> 1)) : (nbase + (row >> 1));
        else            grow = nbase + row;
        size_t g = (size_t)grow * strideB + k0 + koff;
        uint32_t d = smB + (uint32_t)(row * SK + koff) * 2;
        CP_ASYNC(d, (const void*)(hi + g));
        CP_ASYNC(d + PLANE_B, (const void*)(lo + g));
    }
}
__device__ __forceinline__ void ldmA(uint32_t base, int row0, int kb16, int lane, uint32_t* a) {
    uint32_t addr = base + (uint32_t)((row0 + (lane & 15)) * SK + kb16 + (lane >> 4) * 8) * 2;
    ldm_x4(addr, a);
}
__device__ __forceinline__ void ldmB(uint32_t base, int row0, int kb16, int lane, uint32_t* b) {
    int r = row0 + ((lane >> 4) << 3) + (lane & 7);
    int kf = kb16 + ((lane >> 3) & 1) * 8;
    uint32_t addr = base + (uint32_t)(r * SK + kf) * 2;
    ldm_x4(addr, b);
}

// 3-term mma over one k-block (64 k) for one stage
__device__ __forceinline__ void mma_kblock(uint32_t sb, int stage, int m0w, int n0w, int lane,
                                           float acc[4][4][4]) {
    uint32_t smAhi = sb + SM_AHI, smAlo = sb + SM_ALO;
    uint32_t smBhi = sb + SM_B(stage), smBlo = smBhi + PLANE_B;
#pragma unroll
    for (int k16 = 0; k16 < 4; k16++) {
        int kb16 = k16 * 16;
        uint32_t ah[4][4], al[4][4], bh[2][4], bl[2][4];
#pragma unroll
        for (int mi = 0; mi < 4; mi++) ldmA(smAhi, m0w + mi * 16, kb16, lane, ah[mi]);
#pragma unroll
        for (int mi = 0; mi < 4; mi++) ldmA(smAlo, m0w + mi * 16, kb16, lane, al[mi]);
#pragma unroll
        for (int ni = 0; ni < 2; ni++) ldmB(smBhi, n0w + ni * 16, kb16, lane, bh[ni]);
#pragma unroll
        for (int ni = 0; ni < 2; ni++) ldmB(smBlo, n0w + ni * 16, kb16, lane, bl[ni]);
#pragma unroll
        for (int mi = 0; mi < 4; mi++)
#pragma unroll
            for (int n8 = 0; n8 < 4; n8++) {
                int ni = n8 >> 1, hf = (n8 & 1) * 2;
                mma_bf16(acc[mi][n8], ah[mi], bh[ni][hf], bh[ni][hf + 1]);
                mma_bf16(acc[mi][n8], ah[mi], bl[ni][hf], bl[ni][hf + 1]);
                mma_bf16(acc[mi][n8], al[mi], bh[ni][hf], bh[ni][hf + 1]);
            }
    }
}

// ---------------- GEMM1: f = sin(gate+bg)*(val+bv), packed out ----------------
// grid (64, 2): nblk covers 64 feature-pairs, mblk 128 rows. B rows interleaved gate/val.
__global__ void __launch_bounds__(256) k_gemm1_mma(const float* __restrict__ b_up) {
    extern __shared__ __align__(16) char smem[];
    uint32_t sb = smem_u32(smem);
    int tid = threadIdx.x, wid = tid >> 5, lane = tid & 31;
    int m0w = (wid >> 2) * 64, n0w = (wid & 3) * 32;
    int nbase = blockIdx.x * 64;
    int m0 = blockIdx.y * 128;

    float acc[4][4][4];
#pragma unroll
    for (int i = 0; i < 4; i++)
#pragma unroll
        for (int j = 0; j < 4; j++)
#pragma unroll
            for (int q = 0; q < 4; q++) acc[i][j][q] = 0.f;

    uint4 ar[8];
    ldA_regs(g_cn2p, EN, m0, 0, tid, ar);
    cpB<1>(sb + SM_B(0), g_wup_hi, g_wup_lo, EN, 0, tid, nbase);
    CP_COMMIT();
#pragma unroll 1
    for (int kb = 0; kb < 16; kb++) {
        int cur = kb & 1;
        stA_unpack(sb + SM_AHI, sb + SM_ALO, tid, ar);
        if (kb + 1 < 16) {
            ldA_regs(g_cn2p, EN, m0, (kb + 1) * 64, tid, ar);
            cpB<1>(sb + SM_B(cur ^ 1), g_wup_hi, g_wup_lo, EN, (kb + 1) * 64, tid, nbase);
            CP_COMMIT();
            CP_WAIT1();
        } else CP_WAIT0();
        __syncthreads();
        mma_kblock(sb, cur, m0w, n0w, lane, acc);
        __syncthreads();
    }

    // epilogue: (c0,c1)=(gate,val) at row r; (c2,c3) at row r+8
#pragma unroll
    for (int n8 = 0; n8 < 4; n8++) {
        int n = nbase + (n0w >> 1) + n8 * 4 + (lane & 3);
        float bg = b_up[n], bv = b_up[DFFN + n];
#pragma unroll
        for (int mi = 0; mi < 4; mi++) {
            int r = m0 + m0w + mi * 16 + (lane >> 2);
            float f0 = sinf(acc[mi][n8][0] + bg) * (acc[mi][n8][1] + bv);
            float f1 = sinf(acc[mi][n8][2] + bg) * (acc[mi][n8][3] + bv);
            g_fp[(size_t)r * DFFN + n] = pack_bf16split(f0);
            g_fp[(size_t)(r + 8) * DFFN + n] = pack_bf16split(f1);
        }
    }
}

// ---------------- GEMM2 (split-K 8): partial = f @ w_down^T ----------------
// grid (8, 2, 8)
__global__ void __launch_bounds__(256) k_gemm2_mma() {
    extern __shared__ __align__(16) char smem[];
    uint32_t sb = smem_u32(smem);
    int tid = threadIdx.x, wid = tid >> 5, lane = tid & 31;
    int m0w = (wid >> 2) * 64, n0w = (wid & 3) * 32;
    int nbase = blockIdx.x * 128;
    int m0 = blockIdx.y * 128;
    int z = blockIdx.z, kz = z * 512;

    float acc[4][4][4];
#pragma unroll
    for (int i = 0; i < 4; i++)
#pragma unroll
        for (int j = 0; j < 4; j++)
#pragma unroll
            for (int q = 0; q < 4; q++) acc[i][j][q] = 0.f;

    uint4 ar[8];
    ldA_regs(g_fp, DFFN, m0, kz, tid, ar);
    cpB<0>(sb + SM_B(0), g_wdn_hi, g_wdn_lo, DFFN, kz, tid, nbase);
    CP_COMMIT();
#pragma unroll 1
    for (int kb = 0; kb < 8; kb++) {
        int cur = kb & 1;
        stA_unpack(sb + SM_AHI, sb + SM_ALO, tid, ar);
        if (kb + 1 < 8) {
            ldA_regs(g_fp, DFFN, m0, kz + (kb + 1) * 64, tid, ar);
            cpB<0>(sb + SM_B(cur ^ 1), g_wdn_hi, g_wdn_lo, DFFN, kz + (kb + 1) * 64, tid, nbase);
            CP_COMMIT();
            CP_WAIT1();
        } else CP_WAIT0();
        __syncthreads();
        mma_kblock(sb, cur, m0w, n0w, lane, acc);
        __syncthreads();
    }

#pragma unroll
    for (int mi = 0; mi < 4; mi++) {
        int r = m0 + m0w + mi * 16 + (lane >> 2);
#pragma unroll
        for (int n8 = 0; n8 < 4; n8++) {
            int col = nbase + n0w + n8 * 8 + (lane & 3) * 2;
            float* d0 = g_part + ((size_t)z * BN * 64 + r) * EN + col;
            float* d1 = g_part + ((size_t)z * BN * 64 + r + 8) * EN + col;
            *(float2*)d0 = make_float2(acc[mi][n8][0], acc[mi][n8][1]);
            *(float2*)d1 = make_float2(acc[mi][n8][2], acc[mi][n8][3]);
        }
    }
}

// ---------------- epilogue ----------------
__global__ void k_epi(const float* __restrict__ b_down, float* __restrict__ out, int step) {
    int row = blockIdx.x;
    int b = row >> 6, t = row & 63;
    int e = threadIdx.x * 4;
    float4 r2 = *(const float4*)(g_res2 + (size_t)row * EN + e);
    float4 bd = *(const float4*)(b_down + e);
    float4 o;
    o.x = r2.x + bd.x; o.y = r2.y + bd.y; o.z = r2.z + bd.z; o.w = r2.w + bd.w;
#pragma unroll
    for (int z = 0; z < 8; z++) {
        float4 p = *(const float4*)(g_part + ((size_t)z * BN * 64 + row) * EN + e);
        o.x += p.x; o.y += p.y; o.z += p.z; o.w += p.w;
    }
    if (t < 32)
        *(float4*)(out + ((size_t)b * TN + step * 32 + t) * EN + e) = o;
    else
        *(float4*)(g_carry + ((size_t)b * 32 + (t - 32)) * EN + e) = o;
}

// ---------------- launch ----------------
extern "C" void kernel_launch(void* const* d_in, const int* in_sizes, int n_in,
                              void* d_out, int out_size) {
    const float* x      = (const float*)d_in[0];
    const float* ln1_w  = (const float*)d_in[1];
    const float* ln1_b  = (const float*)d_in[2];
    const float* w_fft1 = (const float*)d_in[3];
    const float* w_fft2 = (const float*)d_in[4];
    const float* ln2_w  = (const float*)d_in[5];
    const float* ln2_b  = (const float*)d_in[6];
    const float* w_up   = (const float*)d_in[7];
    const float* b_up   = (const float*)d_in[8];
    const float* w_down = (const float*)d_in[9];
    const float* b_down = (const float*)d_in[10];
    float* out = (float*)d_out;

    static bool attr_set = false;
    if (!attr_set) {
        cudaFuncSetAttribute(k_gemm1_mma, cudaFuncAttributeMaxDynamicSharedMemorySize, SMEM_BYTES);
        cudaFuncSetAttribute(k_gemm2_mma, cudaFuncAttributeMaxDynamicSharedMemorySize, SMEM_BYTES);
        attr_set = true;
    }

    k_convert_w<<<12288, 256>>>(w_up, w_down);
    k_precompute_M<<<16, 256>>>(w_fft1, w_fft2);
    for (int s = 0; s < NSTEP; s++) {
        k_ln1<<<256, 256>>>(x, ln1_w, ln1_b, s);
        k_fftln2<<<256, 256>>>(x, ln2_w, ln2_b, s);
        k_gemm1_mma<<<dim3(64, 2), 256, SMEM_BYTES>>>(b_up);
        k_gemm2_mma<<<dim3(8, 2, 8), 256, SMEM_BYTES>>>();
        k_epi<<<256, 256>>>(b_down, out, s);
    }
}